// round 17
// baseline (speedup 1.0000x reference)
#include <cuda_runtime.h>

// CVCalculator: sliding-window CV, W=60, ddof=1, eps=1e-6.
// flow (16,4096,64) fp32 -> out (16,4096,64), first 59 time rows zero.
//
// Gold-matching cumsum = XLA ReduceWindowRewriter blocked scan, base 16
// (verified R8/R10/R11/R13/R16). Scan arithmetic bitwise-locked.
// Pole-critical: mean = s1/60 (Markstein 2-fma == div.rn), denom = RN add.
// Numerator relaxed (relative ~1e-7).
//
// R17: one thread per 16-block, BOTH kinds, everything register-resident.
// cs never stored: epilogue c-values from registers, p-values (t-60, blocks
// b-4/b-3) via warp shuffle; warp-boundary blocks via a 17KB smem patch.
// NT=256 -> 256-reg budget (no 128-reg pipelining ceiling), smem 27KB.

#define T_   4096
#define NT   256
// smem (floats): TOT 2*16*68 | S2 2*68 | BND 32*136
#define TB   0
#define GBASE 2176
#define BB   2312
#define SMEM_FLOATS (BB + 32 * 136)        // 6664
#define SMEM_BYTES  (SMEM_FLOATS * 4)      // 26656 B

__device__ __forceinline__ float4 f4addv(float4 a, float4 v) {
    float4 r;
    r.x = __fadd_rn(a.x, v.x); r.y = __fadd_rn(a.y, v.y);
    r.z = __fadd_rn(a.z, v.z); r.w = __fadd_rn(a.w, v.w);
    return r;
}
__device__ __forceinline__ float4 f4carry(float4 c, float4 v) {   // fl(c + v)
    float4 r;
    r.x = __fadd_rn(c.x, v.x); r.y = __fadd_rn(c.y, v.y);
    r.z = __fadd_rn(c.z, v.z); r.w = __fadd_rn(c.w, v.w);
    return r;
}
__device__ __forceinline__ float cv_elem(float c1, float p1, float c2, float p2) {
    const float C60 = 0.016666667f;            // fl(1/60)
    float s1 = __fsub_rn(c1, p1);
    float s2 = __fsub_rn(c2, p2);
    float q0   = __fmul_rn(s1, C60);
    float rr   = __fmaf_rn(-60.0f, q0, s1);
    float mean = __fmaf_rn(rr, C60, q0);       // == div.rn(s1,60)
    float denom = __fadd_rn(mean, 1e-6f);      // pole-critical
    float var = __fmul_rn(__fmaf_rn(-s1, mean, s2), 1.0f / 59.0f);
    float std = (var > 0.0f) ? __fmul_rn(var, __frsqrt_rn(var)) : 0.0f;
    return __fdividef(std, denom);
}
__device__ __forceinline__ float4 shfl_up_f4(float4 v, int d) {
    float4 r;
    r.x = __shfl_up_sync(0xffffffffu, v.x, d);
    r.y = __shfl_up_sync(0xffffffffu, v.y, d);
    r.z = __shfl_up_sync(0xffffffffu, v.z, d);
    r.w = __shfl_up_sync(0xffffffffu, v.w, d);
    return r;
}

extern "C" __global__ void __launch_bounds__(NT, 1)
cv_kernel(const float* __restrict__ in, float* __restrict__ out)
{
    __shared__ float S[SMEM_FLOATS];
    const int b    = threadIdx.x;             // block 0..255
    const int w    = b >> 5;
    const int lane = b & 31;
    const int bat  = blockIdx.x >> 4;
    const int fb   = (blockIdx.x & 15) * 4;

    const float* __restrict__ gin  = in  + (size_t)bat * T_ * 64 + fb;
    float* __restrict__       gout = out + (size_t)bat * T_ * 64 + fb;

    // ---- P1: load 16 rows (LDG.128, MLP=16), square, both chains in regs ----
    float4 r1[16], r2[16];
    const float* __restrict__ gp = gin + (size_t)(b << 4) * 64;
    #pragma unroll
    for (int i = 0; i < 16; ++i)
        r1[i] = *reinterpret_cast<const float4*>(gp + (size_t)i * 64);
    #pragma unroll
    for (int i = 0; i < 16; ++i) {
        r2[i].x = __fmul_rn(r1[i].x, r1[i].x);
        r2[i].y = __fmul_rn(r1[i].y, r1[i].y);
        r2[i].z = __fmul_rn(r1[i].z, r1[i].z);
        r2[i].w = __fmul_rn(r1[i].w, r1[i].w);
    }
    #pragma unroll
    for (int i = 1; i < 16; ++i) r1[i] = f4addv(r1[i - 1], r1[i]);
    #pragma unroll
    for (int i = 1; i < 16; ++i) r2[i] = f4addv(r2[i - 1], r2[i]);

    // block totals -> TOT[kind][group][i]  (stride 68, conflict-free)
    {
        const int g = b >> 4, ii = b & 15;
        *reinterpret_cast<float4*>(S + TB + (0 * 16 + g) * 68 + ii * 4) = r1[15];
        *reinterpret_cast<float4*>(S + TB + (1 * 16 + g) * 68 + ii * 4) = r2[15];
    }
    __syncthreads();

    // ---- P2: scan totals within 16-groups (warp 0; prefetch then chain) ----
    if (b < 32) {
        const int kk = b >> 4, g = b & 15;
        float* __restrict__ c = S + TB + (kk * 16 + g) * 68;
        float4 v[16];
        #pragma unroll
        for (int i = 0; i < 16; ++i)
            v[i] = *reinterpret_cast<const float4*>(c + 4 * i);
        #pragma unroll
        for (int i = 1; i < 16; ++i) v[i] = f4addv(v[i - 1], v[i]);
        #pragma unroll
        for (int i = 0; i < 16; ++i)
            *reinterpret_cast<float4*>(c + 4 * i) = v[i];   // inner1 inclusive
        *reinterpret_cast<float4*>(S + GBASE + kk * 68 + g * 4) = v[15];
    }
    __syncwarp();
    // ---- P3: scan 16 group totals per kind (lanes 0,1) ----
    if (b < 2) {
        float* __restrict__ gbuf = S + GBASE + b * 68;
        float4 v[16];
        #pragma unroll
        for (int g = 0; g < 16; ++g)
            v[g] = *reinterpret_cast<const float4*>(gbuf + 4 * g);
        #pragma unroll
        for (int g = 1; g < 16; ++g) v[g] = f4addv(v[g - 1], v[g]);
        #pragma unroll
        for (int g = 0; g < 16; ++g)
            *reinterpret_cast<float4*>(gbuf + 4 * g) = v[g]; // S2 inclusive
    }
    __syncthreads();

    // ---- carry: S1[b-1] = fl(S2[pg-1] + inner1[b-1]); cs = fl(carry + r) ----
    if (b > 0) {
        const int pb = b - 1, pg = pb >> 4, pi = pb & 15;
        float4 c1 = *reinterpret_cast<const float4*>(
            S + TB + (0 * 16 + pg) * 68 + pi * 4);
        float4 c2 = *reinterpret_cast<const float4*>(
            S + TB + (1 * 16 + pg) * 68 + pi * 4);
        if (pg > 0) {
            float4 s1v = *reinterpret_cast<const float4*>(S + GBASE + 0 * 68 + (pg - 1) * 4);
            float4 s2v = *reinterpret_cast<const float4*>(S + GBASE + 1 * 68 + (pg - 1) * 4);
            c1 = f4carry(s1v, c1);
            c2 = f4carry(s2v, c2);
        }
        #pragma unroll
        for (int i = 0; i < 16; ++i) r1[i] = f4carry(c1, r1[i]);
        #pragma unroll
        for (int i = 0; i < 16; ++i) r2[i] = f4carry(c2, r2[i]);
    }

    // ---- boundary patch: lanes 28-31 publish their cs arrays ----
    if (lane >= 28) {
        float* __restrict__ bp = S + BB + (w * 4 + (lane - 28)) * 136;
        #pragma unroll
        for (int i = 0; i < 16; ++i) {
            *reinterpret_cast<float4*>(bp + i * 4)      = r1[i];
            *reinterpret_cast<float4*>(bp + 68 + i * 4) = r2[i];
        }
    }
    __syncthreads();

    // ---- epilogue: c from registers, p via shfl (smem patch at warp seams) ----
    #pragma unroll
    for (int i = 0; i < 16; ++i) {
        const int t = (b << 4) + i;
        const int d = (i <= 11) ? 4 : 3;
        const int j = (i <= 11) ? (i + 4) : (i - 12);
        float4 p1 = shfl_up_f4(r1[j], d);
        float4 p2 = shfl_up_f4(r2[j], d);
        if (lane < d && w > 0) {
            const int slot = (w - 1) * 4 + lane + ((i <= 11) ? 0 : 1);
            const float* __restrict__ bp = S + BB + slot * 136;
            p1 = *reinterpret_cast<const float4*>(bp + j * 4);
            p2 = *reinterpret_cast<const float4*>(bp + 68 + j * 4);
        }
        float4 o;
        if (t < 59) {
            o = make_float4(0.f, 0.f, 0.f, 0.f);
        } else {
            if (t == 59) {                     // window [0,59]: p = 0
                p1 = make_float4(0.f, 0.f, 0.f, 0.f);
                p2 = make_float4(0.f, 0.f, 0.f, 0.f);
            }
            o.x = cv_elem(r1[i].x, p1.x, r2[i].x, p2.x);
            o.y = cv_elem(r1[i].y, p1.y, r2[i].y, p2.y);
            o.z = cv_elem(r1[i].z, p1.z, r2[i].z, p2.z);
            o.w = cv_elem(r1[i].w, p1.w, r2[i].w, p2.w);
        }
        *reinterpret_cast<float4*>(gout + (size_t)t * 64) = o;
    }
}

extern "C" void kernel_launch(void* const* d_in, const int* in_sizes, int n_in,
                              void* d_out, int out_size) {
    (void)in_sizes; (void)n_in; (void)out_size;
    cv_kernel<<<256, NT>>>((const float*)d_in[0], (float*)d_out);
}